// round 2
// baseline (speedup 1.0000x reference)
#include <cuda_runtime.h>
#include <math.h>

// Problem constants
#define Bz  64
#define Tz  512
#define Iz  256
#define Hz  512
#define FH  2048   // 4*H
#define NCTA 148
#define NTHR (NCTA * 128)

// ---------------- device scratch (no allocations allowed) ----------------
__device__ float g_A0[(size_t)Tz * FH * Bz];   // x @ Wx0 + bh0, transposed [t][col][b]
__device__ float g_P0[4 * FH * Bz];            // layer0 K-split partials
__device__ float g_P1[8 * FH * Bz];            // layer1 K-split partials
__device__ float g_h0[Hz * Bz];                // states, transposed [H][B]
__device__ float g_c0[Hz * Bz];
__device__ float g_h1[Hz * Bz];
__device__ float g_c1[Hz * Bz];
__device__ float g_s0[2 * Hz * Bz];            // double-buffered spikes
__device__ unsigned g_bar;                     // grid barrier counter

__device__ __forceinline__ float sigf(float x) { return 1.0f / (1.0f + __expf(-x)); }

// Grid-wide barrier: counter monotonically increases; target = phase * NCTA.
__device__ __forceinline__ void grid_bar(unsigned target) {
    __syncthreads();
    if (threadIdx.x == 0) {
        asm volatile("red.release.gpu.global.add.u32 [%0], 1;"
                     :: "l"(&g_bar) : "memory");
        unsigned v;
        do {
            asm volatile("ld.acquire.gpu.global.u32 %0, [%1];"
                         : "=r"(v) : "l"(&g_bar) : "memory");
        } while (v < target);
    }
    __syncthreads();
}

// ---------------- init: zero states + barrier each launch ----------------
__global__ void k_init() {
    int i = blockIdx.x * 256 + threadIdx.x;
    if (i == 0) g_bar = 0;
    if (i < Hz * Bz) { g_h0[i] = 0.f; g_c0[i] = 0.f; g_h1[i] = 0.f; g_c1[i] = 0.f; }
    if (i < 2 * Hz * Bz) g_s0[i] = 0.f;
}

// ---------------- phase A: A0T[t][col][b] = bh0[col] + sum_i x[b][t][i]*Wx0[i][col]
__global__ __launch_bounds__(128) void k_phaseA(const float* __restrict__ x,
                                                const float* __restrict__ Wx0,
                                                const float* __restrict__ bh0) {
    __shared__ float ws[64][64];
    __shared__ float xs[64][68];
    int colTile = blockIdx.x;
    int t       = blockIdx.y;
    int tid = threadIdx.x;
    int tc = tid & 7;
    int tb = tid >> 3;
    int colBase = colTile * 64;
    float acc[8][4];
#pragma unroll
    for (int a = 0; a < 8; a++)
#pragma unroll
        for (int b = 0; b < 4; b++) acc[a][b] = 0.f;

    for (int kt = 0; kt < 4; kt++) {
        int kb = kt * 64;
        for (int i = tid; i < 64 * 16; i += 128) {
            int row = i >> 4, c4 = (i & 15) << 2;
            *(float4*)&ws[row][c4] =
                *(const float4*)&Wx0[(size_t)(kb + row) * FH + colBase + c4];
        }
        {
            int b = tid >> 1, half = tid & 1;
            const float* xrow = x + ((size_t)b * Tz + t) * Iz + kb + half * 32;
#pragma unroll
            for (int q = 0; q < 8; q++) {
                float4 v = *(const float4*)(xrow + q * 4);
                int i0 = half * 32 + q * 4;
                xs[i0 + 0][b] = v.x; xs[i0 + 1][b] = v.y;
                xs[i0 + 2][b] = v.z; xs[i0 + 3][b] = v.w;
            }
        }
        __syncthreads();
#pragma unroll 16
        for (int k = 0; k < 64; k++) {
            float4 w0 = *(const float4*)&ws[k][tc * 8];
            float4 w1 = *(const float4*)&ws[k][tc * 8 + 4];
            float4 hv = *(const float4*)&xs[k][tb * 4];
            float wr[8] = {w0.x, w0.y, w0.z, w0.w, w1.x, w1.y, w1.z, w1.w};
            float hr[4] = {hv.x, hv.y, hv.z, hv.w};
#pragma unroll
            for (int ci = 0; ci < 8; ci++)
#pragma unroll
                for (int bi = 0; bi < 4; bi++) acc[ci][bi] += wr[ci] * hr[bi];
        }
        __syncthreads();
    }
    float* outp = g_A0 + (size_t)t * (FH * Bz) + (size_t)colBase * Bz;
#pragma unroll
    for (int ci = 0; ci < 8; ci++) {
        float bias = bh0[colBase + tc * 8 + ci];
        float4 v = {acc[ci][0] + bias, acc[ci][1] + bias,
                    acc[ci][2] + bias, acc[ci][3] + bias};
        *(float4*)&outp[(tc * 8 + ci) * Bz + tb * 4] = v;
    }
}

// ---------------- persistent recurrent kernel: 148 CTAs x 128 threads ----------------
__global__ __launch_bounds__(128) void k_persist(
    const float* __restrict__ Wh0, const float* __restrict__ Wx1,
    const float* __restrict__ Wh1, const float* __restrict__ bh1,
    float* __restrict__ out)
{
    __shared__ float ws[64][64];
    __shared__ float hs[64][64];
    const int tid = threadIdx.x;
    const int cta = blockIdx.x;
    const int tc  = tid & 7;
    const int tb  = tid >> 3;
    const int gid = cta * 128 + tid;
    unsigned ph = 0;

    for (int t = 0; t <= Tz; t++) {
        // ========== GEMM phase: gemm0(t) [h0@Wh0] + gemm1(t-1) [[s0,h1]@[Wx1;Wh1]]
        for (int j = cta; j < 384; j += NCTA) {
            const float *W, *S; float *P;
            int colBase; bool valid;
            if (j < 128) {                       // layer0, K=512 in 4x128
                valid = (t < Tz);
                colBase = (j & 31) * 64;
                int kb = (j >> 5) * 128;
                W = Wh0 + (size_t)kb * FH;
                S = g_h0 + kb * Bz;
                P = g_P0 + (size_t)(j >> 5) * (FH * Bz);
            } else {                             // layer1, K=1024 in 8x128
                valid = (t > 0);
                int i = j - 128;
                colBase = (i & 31) * 64;
                int ks = i >> 5, kb = ks * 128;
                if (kb < Hz) {
                    W = Wx1 + (size_t)kb * FH;
                    S = g_s0 + ((t - 1) & 1) * (Hz * Bz) + kb * Bz;
                } else {
                    W = Wh1 + (size_t)(kb - Hz) * FH;
                    S = g_h1 + (kb - Hz) * Bz;
                }
                P = g_P1 + (size_t)ks * (FH * Bz);
            }
            if (valid) {    // uniform per CTA — __syncthreads inside is safe
                float acc[8][4];
#pragma unroll
                for (int a = 0; a < 8; a++)
#pragma unroll
                    for (int b = 0; b < 4; b++) acc[a][b] = 0.f;
                for (int kt = 0; kt < 2; kt++) {
                    for (int i2 = tid; i2 < 64 * 16; i2 += 128) {
                        int row = i2 >> 4, c4 = (i2 & 15) << 2;
                        *(float4*)&ws[row][c4] =
                            *(const float4*)&W[(size_t)(kt * 64 + row) * FH + colBase + c4];
                        *(float4*)&hs[row][c4] =
                            __ldcg((const float4*)&S[(kt * 64 + row) * Bz + c4]);
                    }
                    __syncthreads();
#pragma unroll 16
                    for (int k = 0; k < 64; k++) {
                        float4 w0 = *(const float4*)&ws[k][tc * 8];
                        float4 w1 = *(const float4*)&ws[k][tc * 8 + 4];
                        float4 hv = *(const float4*)&hs[k][tb * 4];
                        float wr[8] = {w0.x, w0.y, w0.z, w0.w, w1.x, w1.y, w1.z, w1.w};
                        float hr[4] = {hv.x, hv.y, hv.z, hv.w};
#pragma unroll
                        for (int ci = 0; ci < 8; ci++)
#pragma unroll
                            for (int bi = 0; bi < 4; bi++) acc[ci][bi] += wr[ci] * hr[bi];
                    }
                    __syncthreads();
                }
#pragma unroll
                for (int ci = 0; ci < 8; ci++) {
                    float4 v = {acc[ci][0], acc[ci][1], acc[ci][2], acc[ci][3]};
                    __stcg((float4*)&P[(size_t)(colBase + tc * 8 + ci) * Bz + tb * 4], v);
                }
            }
        }
        grid_bar(++ph * NCTA);

        // ========== gate phase: gate0(t) + gate1(t-1)
        for (int idx = gid; idx < Hz * Bz; idx += NTHR) {
            int b  = idx & 63;
            int jj = idx >> 6;
            int o   = idx;                       // jj*Bz + b
            int o_f = (Hz + jj) * Bz + b;
            int o_g = (2 * Hz + jj) * Bz + b;
            int o_o = (3 * Hz + jj) * Bz + b;

            if (t < Tz) {    // layer-0 cell + ALIF neuron, step t
                const float* A = g_A0 + (size_t)t * (FH * Bz);
                float ig = __ldcs(A + o), fg = __ldcs(A + o_f);
                float gg = __ldcs(A + o_g), og = __ldcs(A + o_o);
#pragma unroll
                for (int s = 0; s < 4; s++) {
                    const float* P = g_P0 + (size_t)s * (FH * Bz);
                    ig += __ldcg(P + o);   fg += __ldcg(P + o_f);
                    gg += __ldcg(P + o_g); og += __ldcg(P + o_o);
                }
                float c_old = g_c0[o];
                float cn = sigf(fg) * c_old + sigf(ig) * tanhf(gg);
                float hn = sigf(og) * tanhf(cn);
                float s_old = g_s0[((t & 1) ^ 1) * (Hz * Bz) + o];
                float mem = s_old * 0.2f * (1.0f - s_old) + hn;
                float sn = (mem > 0.5f) ? 1.0f : 0.0f;
                g_c0[o] = cn;
                g_h0[o] = mem;
                g_s0[(t & 1) * (Hz * Bz) + o] = sn;
            }
            if (t > 0) {     // layer-1 cell + output neuron, step t-1
                int tp = t - 1;
                float ig = bh1[jj], fg = bh1[Hz + jj];
                float gg = bh1[2 * Hz + jj], og = bh1[3 * Hz + jj];
#pragma unroll
                for (int s = 0; s < 8; s++) {
                    const float* P = g_P1 + (size_t)s * (FH * Bz);
                    ig += __ldcg(P + o);   fg += __ldcg(P + o_f);
                    gg += __ldcg(P + o_g); og += __ldcg(P + o_o);
                }
                float c_old = g_c1[o];
                float cn = sigf(fg) * c_old + sigf(ig) * tanhf(gg);
                float hraw = sigf(og) * tanhf(cn);
                float sp = g_s0[(tp & 1) * (Hz * Bz) + o];
                float h1 = hraw * 0.2f + sp;
                g_c1[o] = cn;
                g_h1[o] = h1;
                out[((size_t)b * Tz + tp) * Hz + jj] = h1;
            }
        }
        grid_bar(++ph * NCTA);
    }

    // ========== finalize: final states (all values written by this same thread)
    for (int idx = gid; idx < Hz * Bz; idx += NTHR) {
        int b = idx & 63, jj = idx >> 6;
        size_t base = (size_t)Bz * Tz * Hz;
        size_t bj = (size_t)b * Hz + jj;
        out[base + bj]          = g_s0[((Tz - 1) & 1) * (Hz * Bz) + idx]; // s0
        out[base +  32768 + bj] = 0.0f;                                   // s1
        out[base +  65536 + bj] = g_h0[idx];                              // h0
        out[base +  98304 + bj] = g_h1[idx];                              // h1
        out[base + 131072 + bj] = g_c0[idx];                              // c0
        out[base + 163840 + bj] = g_c1[idx];                              // c1
    }
}

// ---------------- launch: 3 graph nodes ----------------
extern "C" void kernel_launch(void* const* d_in, const int* in_sizes, int n_in,
                              void* d_out, int out_size) {
    const float* x   = (const float*)d_in[0];
    const float* Wx0 = (const float*)d_in[1];
    const float* Wh0 = (const float*)d_in[2];
    const float* bh0 = (const float*)d_in[3];
    const float* Wx1 = (const float*)d_in[4];
    const float* Wh1 = (const float*)d_in[5];
    const float* bh1 = (const float*)d_in[6];
    float* out = (float*)d_out;

    k_init<<<256, 256>>>();
    k_phaseA<<<dim3(32, Tz), 128>>>(x, Wx0, bh0);
    k_persist<<<NCTA, 128>>>(Wh0, Wx1, Wh1, bh1, out);
}

// round 4
// speedup vs baseline: 1.3079x; 1.3079x over previous
#include <cuda_runtime.h>
#include <math.h>

// Problem constants
#define Bz  64
#define Tz  512
#define Iz  256
#define Hz  512
#define FH  2048   // 4*H
#define NCTA 148
#define NTHR (NCTA * 128)
#define HB  (Hz * Bz)

// ---------------- device scratch (no allocations allowed) ----------------
__device__ float g_A0[(size_t)Tz * FH * Bz];   // x @ Wx0 + bh0, transposed [t][col][b]
__device__ float g_P0[4 * FH * Bz];            // layer0 K-split partials
__device__ float g_P1[8 * FH * Bz];            // layer1 K-split partials
__device__ float g_h0[HB];                     // states, transposed [H][B]
__device__ float g_c0[HB];
__device__ float g_h1[HB];
__device__ float g_c1[HB];
__device__ float g_s0[2 * HB];                 // double-buffered spikes
__device__ unsigned g_bar;                     // grid barrier counter

__device__ __forceinline__ float sigf(float x) { return 1.0f / (1.0f + __expf(-x)); }

// Grid-wide barrier: counter monotonically increases; target = phase * NCTA.
__device__ __forceinline__ void grid_bar(unsigned target) {
    __syncthreads();
    if (threadIdx.x == 0) {
        asm volatile("red.release.gpu.global.add.u32 [%0], 1;"
                     :: "l"(&g_bar) : "memory");
        unsigned v;
        do {
            asm volatile("ld.acquire.gpu.global.u32 %0, [%1];"
                         : "=r"(v) : "l"(&g_bar) : "memory");
        } while (v < target);
    }
    __syncthreads();
}

// ---------------- init ----------------
__global__ void k_init() {
    int i = blockIdx.x * 256 + threadIdx.x;
    if (i == 0) g_bar = 0;
    if (i < HB) { g_h0[i] = 0.f; g_c0[i] = 0.f; g_h1[i] = 0.f; g_c1[i] = 0.f; }
    if (i < 2 * HB) g_s0[i] = 0.f;
}

// ---------------- phase A: A0T[t][col][b] = bh0[col] + sum_i x[b][t][i]*Wx0[i][col]
__global__ __launch_bounds__(128) void k_phaseA(const float* __restrict__ x,
                                                const float* __restrict__ Wx0,
                                                const float* __restrict__ bh0) {
    __shared__ float ws[64][64];
    __shared__ float xs[64][68];
    int colTile = blockIdx.x;
    int t       = blockIdx.y;
    int tid = threadIdx.x;
    int tc = tid & 7;
    int tb = tid >> 3;
    int colBase = colTile * 64;
    float acc[8][4];
#pragma unroll
    for (int a = 0; a < 8; a++)
#pragma unroll
        for (int b = 0; b < 4; b++) acc[a][b] = 0.f;

    for (int kt = 0; kt < 4; kt++) {
        int kb = kt * 64;
        for (int i = tid; i < 64 * 16; i += 128) {
            int row = i >> 4, c4 = (i & 15) << 2;
            *(float4*)&ws[row][c4] =
                *(const float4*)&Wx0[(size_t)(kb + row) * FH + colBase + c4];
        }
        {
            int b = tid >> 1, half = tid & 1;
            const float* xrow = x + ((size_t)b * Tz + t) * Iz + kb + half * 32;
#pragma unroll
            for (int q = 0; q < 8; q++) {
                float4 v = *(const float4*)(xrow + q * 4);
                int i0 = half * 32 + q * 4;
                xs[i0 + 0][b] = v.x; xs[i0 + 1][b] = v.y;
                xs[i0 + 2][b] = v.z; xs[i0 + 3][b] = v.w;
            }
        }
        __syncthreads();
#pragma unroll 16
        for (int k = 0; k < 64; k++) {
            float4 w0 = *(const float4*)&ws[k][tc * 8];
            float4 w1 = *(const float4*)&ws[k][tc * 8 + 4];
            float4 hv = *(const float4*)&xs[k][tb * 4];
            float wr[8] = {w0.x, w0.y, w0.z, w0.w, w1.x, w1.y, w1.z, w1.w};
            float hr[4] = {hv.x, hv.y, hv.z, hv.w};
#pragma unroll
            for (int ci = 0; ci < 8; ci++)
#pragma unroll
                for (int bi = 0; bi < 4; bi++) acc[ci][bi] += wr[ci] * hr[bi];
        }
        __syncthreads();
    }
    float* outp = g_A0 + (size_t)t * (FH * Bz) + (size_t)colBase * Bz;
#pragma unroll
    for (int ci = 0; ci < 8; ci++) {
        float bias = bh0[colBase + tc * 8 + ci];
        float4 v = {acc[ci][0] + bias, acc[ci][1] + bias,
                    acc[ci][2] + bias, acc[ci][3] + bias};
        *(float4*)&outp[(tc * 8 + ci) * Bz + tb * 4] = v;
    }
}

// ---------------- persistent recurrent kernel: 148 CTAs x 128 threads ----------------
// Dynamic smem: wAll[3][128][64] weights (persist across steps) + hbuf[2][64][64] state.
#define SMEM_BYTES ((3 * 128 * 64 + 2 * 64 * 64) * 4)

__global__ __launch_bounds__(128) void k_persist(
    const float* __restrict__ Wh0, const float* __restrict__ Wx1,
    const float* __restrict__ Wh1, const float* __restrict__ bh1,
    float* __restrict__ out)
{
    extern __shared__ float smem[];
    float* wAll = smem;                   // 3 * 8192 floats
    float* hbuf = smem + 3 * 8192;        // 2 * 4096 floats

    const int tid = threadIdx.x;
    const int cta = blockIdx.x;
    const int tc  = tid & 7;
    const int tb  = tid >> 3;
    const int gid = cta * 128 + tid;
    unsigned ph = 0;

    // ---- fixed job descriptors for this CTA (identical every step) ----
    int   njobs = 0;
    const float* jSbase[3];   // state base (non-s0 part)
    float*       jP[3];       // partial output base (already includes colBase)
    int   jType[3];           // 0: layer0 (valid t<Tz), 1: layer1 (valid t>0)
    int   jS0off[3];          // >=0: S = g_s0 + parity*HB + jS0off ; -1: use jSbase
    for (int q = 0; q < 3; q++) {
        int j = cta + q * NCTA;
        if (j >= 384) break;
        const float* W; int colBase;
        if (j < 128) {                        // layer0, K=512 in 4x128
            colBase = (j & 31) * 64;
            int ks = j >> 5, kb = ks * 128;
            W = Wh0 + (size_t)kb * FH;
            jSbase[q] = g_h0 + kb * Bz;  jS0off[q] = -1;
            jP[q] = g_P0 + (size_t)ks * (FH * Bz) + (size_t)colBase * Bz;
            jType[q] = 0;
        } else {                              // layer1, K=1024 in 8x128
            int i = j - 128;
            colBase = (i & 31) * 64;
            int ks = i >> 5, kb = ks * 128;
            if (kb < Hz) { W = Wx1 + (size_t)kb * FH;       jSbase[q] = 0;                 jS0off[q] = kb * Bz; }
            else         { W = Wh1 + (size_t)(kb - Hz) * FH; jSbase[q] = g_h1 + (kb - Hz) * Bz; jS0off[q] = -1;  }
            jP[q] = g_P1 + (size_t)ks * (FH * Bz) + (size_t)colBase * Bz;
            jType[q] = 1;
        }
        // preload weight tile into smem (persists across all steps)
        float* wd = wAll + q * 8192;
        for (int i2 = tid; i2 < 2048; i2 += 128) {        // 2048 float4s
            int row = i2 >> 4, c4 = (i2 & 15) << 2;
            *(float4*)&wd[row * 64 + c4] =
                *(const float4*)&W[(size_t)row * FH + colBase + c4];
        }
        njobs = q + 1;
    }
    __syncthreads();

    const int srow = tid >> 4;          // 0..7  (state-load row base)
    const int sc4  = (tid & 15) << 2;   // 0..60

    for (int t = 0; t <= Tz; t++) {
        // ---- build list of valid (job, kt) units for this step ----
        int units[6], nu = 0;
        for (int q = 0; q < njobs; q++) {
            bool valid = jType[q] ? (t > 0) : (t < Tz);
            if (valid) { units[nu++] = q * 2; units[nu++] = q * 2 + 1; }
        }

        float acc[8][4];
        float4 r[8];

        // prefetch state for unit 0 (full 64 rows: srow + 8*m, m=0..7)
        if (nu > 0) {
            int q = units[0] >> 1, kt = units[0] & 1;
            const float* S = (jS0off[q] >= 0)
                ? g_s0 + ((t - 1) & 1) * HB + jS0off[q] : jSbase[q];
            S += kt * 64 * Bz;
#pragma unroll
            for (int m = 0; m < 8; m++)
                r[m] = __ldcg((const float4*)&S[(srow + 8 * m) * Bz + sc4]);
        }

        for (int u = 0; u < nu; u++) {
            int q  = units[u] >> 1;
            int kt = units[u] & 1;
            float* hb = hbuf + (u & 1) * 4096;
            // store prefetched state tile (full coverage)
#pragma unroll
            for (int m = 0; m < 8; m++)
                *(float4*)&hb[(srow + 8 * m) * 64 + sc4] = r[m];
            __syncthreads();
            // prefetch next unit's state (overlaps with compute below)
            if (u + 1 < nu) {
                int q2 = units[u + 1] >> 1, kt2 = units[u + 1] & 1;
                const float* S = (jS0off[q2] >= 0)
                    ? g_s0 + ((t - 1) & 1) * HB + jS0off[q2] : jSbase[q2];
                S += kt2 * 64 * Bz;
#pragma unroll
                for (int m = 0; m < 8; m++)
                    r[m] = __ldcg((const float4*)&S[(srow + 8 * m) * Bz + sc4]);
            }
            // fresh accumulators at kt==0
            if (kt == 0) {
#pragma unroll
                for (int a = 0; a < 8; a++)
#pragma unroll
                    for (int b = 0; b < 4; b++) acc[a][b] = 0.f;
            }
            const float* wq = wAll + q * 8192 + kt * 4096;
#pragma unroll 16
            for (int k = 0; k < 64; k++) {
                float4 w0 = *(const float4*)&wq[k * 64 + tc * 8];
                float4 w1 = *(const float4*)&wq[k * 64 + tc * 8 + 4];
                float4 hv = *(const float4*)&hb[k * 64 + tb * 4];
                float wr[8] = {w0.x, w0.y, w0.z, w0.w, w1.x, w1.y, w1.z, w1.w};
                float hr[4] = {hv.x, hv.y, hv.z, hv.w};
#pragma unroll
                for (int ci = 0; ci < 8; ci++)
#pragma unroll
                    for (int bi = 0; bi < 4; bi++) acc[ci][bi] += wr[ci] * hr[bi];
            }
            // write partials after kt==1
            if (kt == 1) {
                float* P = jP[q];
#pragma unroll
                for (int ci = 0; ci < 8; ci++) {
                    float4 v = {acc[ci][0], acc[ci][1], acc[ci][2], acc[ci][3]};
                    __stcg((float4*)&P[(size_t)(tc * 8 + ci) * Bz + tb * 4], v);
                }
            }
            __syncthreads();   // hbuf[u&1] free for reuse at u+2
        }
        grid_bar(++ph * NCTA);

        // ========== gate phase: gate0(t) + gate1(t-1)
        for (int idx = gid; idx < HB; idx += NTHR) {
            int b  = idx & 63;
            int jj = idx >> 6;
            int o   = idx;
            int o_f = (Hz + jj) * Bz + b;
            int o_g = (2 * Hz + jj) * Bz + b;
            int o_o = (3 * Hz + jj) * Bz + b;

            if (t < Tz) {    // layer-0 cell + ALIF neuron, step t
                const float* A = g_A0 + (size_t)t * (FH * Bz);
                float ig = __ldcs(A + o), fg = __ldcs(A + o_f);
                float gg = __ldcs(A + o_g), og = __ldcs(A + o_o);
#pragma unroll
                for (int s = 0; s < 4; s++) {
                    const float* P = g_P0 + (size_t)s * (FH * Bz);
                    ig += __ldcg(P + o);   fg += __ldcg(P + o_f);
                    gg += __ldcg(P + o_g); og += __ldcg(P + o_o);
                }
                float c_old = g_c0[o];
                float cn = sigf(fg) * c_old + sigf(ig) * tanhf(gg);
                float hn = sigf(og) * tanhf(cn);
                float s_old = g_s0[((t & 1) ^ 1) * HB + o];
                float mem = s_old * 0.2f * (1.0f - s_old) + hn;
                float sn = (mem > 0.5f) ? 1.0f : 0.0f;
                g_c0[o] = cn;
                g_h0[o] = mem;
                g_s0[(t & 1) * HB + o] = sn;
            }
            if (t > 0) {     // layer-1 cell + output neuron, step t-1
                int tp = t - 1;
                float ig = bh1[jj], fg = bh1[Hz + jj];
                float gg = bh1[2 * Hz + jj], og = bh1[3 * Hz + jj];
#pragma unroll
                for (int s = 0; s < 8; s++) {
                    const float* P = g_P1 + (size_t)s * (FH * Bz);
                    ig += __ldcg(P + o);   fg += __ldcg(P + o_f);
                    gg += __ldcg(P + o_g); og += __ldcg(P + o_o);
                }
                float c_old = g_c1[o];
                float cn = sigf(fg) * c_old + sigf(ig) * tanhf(gg);
                float hraw = sigf(og) * tanhf(cn);
                float sp = g_s0[(tp & 1) * HB + o];
                float h1 = hraw * 0.2f + sp;
                g_c1[o] = cn;
                g_h1[o] = h1;
                out[((size_t)b * Tz + tp) * Hz + jj] = h1;
            }
        }
        grid_bar(++ph * NCTA);
    }

    // ========== finalize
    for (int idx = gid; idx < HB; idx += NTHR) {
        int b = idx & 63, jj = idx >> 6;
        size_t base = (size_t)Bz * Tz * Hz;
        size_t bj = (size_t)b * Hz + jj;
        out[base + bj]          = g_s0[((Tz - 1) & 1) * HB + idx];  // s0
        out[base +  32768 + bj] = 0.0f;                             // s1
        out[base +  65536 + bj] = g_h0[idx];                        // h0
        out[base +  98304 + bj] = g_h1[idx];                        // h1
        out[base + 131072 + bj] = g_c0[idx];                        // c0
        out[base + 163840 + bj] = g_c1[idx];                        // c1
    }
}

// ---------------- launch: 3 graph nodes ----------------
extern "C" void kernel_launch(void* const* d_in, const int* in_sizes, int n_in,
                              void* d_out, int out_size) {
    const float* x   = (const float*)d_in[0];
    const float* Wx0 = (const float*)d_in[1];
    const float* Wh0 = (const float*)d_in[2];
    const float* bh0 = (const float*)d_in[3];
    const float* Wx1 = (const float*)d_in[4];
    const float* Wh1 = (const float*)d_in[5];
    const float* bh1 = (const float*)d_in[6];
    float* out = (float*)d_out;

    static int smem_set = 0;
    if (!smem_set) {
        cudaFuncSetAttribute(k_persist,
                             cudaFuncAttributeMaxDynamicSharedMemorySize,
                             SMEM_BYTES);
        smem_set = 1;
    }

    k_init<<<256, 256>>>();
    k_phaseA<<<dim3(32, Tz), 128>>>(x, Wx0, bh0);
    k_persist<<<NCTA, 128, SMEM_BYTES>>>(Wh0, Wx1, Wh1, bh1, out);
}

// round 6
// speedup vs baseline: 1.3560x; 1.0368x over previous
#include <cuda_runtime.h>
#include <math.h>

// Problem constants
#define Bz  64
#define Tz  512
#define Iz  256
#define Hz  512
#define FH  2048   // 4*H
#define NCTA 148
#define HB  (Hz * Bz)
#define OUTBASE (Bz * Tz * Hz)   // 16777216

// ---------------- device scratch (no allocations allowed) ----------------
__device__ float g_A0[(size_t)Tz * FH * Bz];   // x@Wx0+bh0, [t][col][b]
__device__ float g_h0[2 * HB];                 // parity-buffered states, [H][B]
__device__ float g_h1[2 * HB];
__device__ float g_s0[2 * HB];
__device__ unsigned g_bar;

__device__ __forceinline__ float sigf(float x) { return 1.0f / (1.0f + __expf(-x)); }

__device__ __forceinline__ void grid_bar(unsigned target) {
    __syncthreads();
    if (threadIdx.x == 0) {
        asm volatile("red.release.gpu.global.add.u32 [%0], 1;" :: "l"(&g_bar) : "memory");
        unsigned v;
        do {
            asm volatile("ld.acquire.gpu.global.u32 %0, [%1];" : "=r"(v) : "l"(&g_bar) : "memory");
        } while (v < target);
    }
    __syncthreads();
}

// ---------------- phase A (+ state init in y==0 blocks) ----------------
__global__ __launch_bounds__(128) void k_phaseA(const float* __restrict__ x,
                                                const float* __restrict__ Wx0,
                                                const float* __restrict__ bh0) {
    __shared__ float ws[64][64];
    __shared__ float xs[64][68];
    int colTile = blockIdx.x;
    int t       = blockIdx.y;
    int tid = threadIdx.x;

    if (t == 0) {   // init states + barrier (32 blocks x 128 thr)
        int g = colTile * 128 + tid;             // 0..4095
        if (g == 0) g_bar = 0;
        for (int i = g; i < 2 * HB; i += 4096) { g_h0[i] = 0.f; g_h1[i] = 0.f; g_s0[i] = 0.f; }
    }

    int tc = tid & 7;
    int tb = tid >> 3;
    int colBase = colTile * 64;
    float acc[8][4];
#pragma unroll
    for (int a = 0; a < 8; a++)
#pragma unroll
        for (int b = 0; b < 4; b++) acc[a][b] = 0.f;

    for (int kt = 0; kt < 4; kt++) {
        int kb = kt * 64;
        for (int i = tid; i < 64 * 16; i += 128) {
            int row = i >> 4, c4 = (i & 15) << 2;
            *(float4*)&ws[row][c4] =
                *(const float4*)&Wx0[(size_t)(kb + row) * FH + colBase + c4];
        }
        {
            int b = tid >> 1, half = tid & 1;
            const float* xrow = x + ((size_t)b * Tz + t) * Iz + kb + half * 32;
#pragma unroll
            for (int q = 0; q < 8; q++) {
                float4 v = *(const float4*)(xrow + q * 4);
                int i0 = half * 32 + q * 4;
                xs[i0 + 0][b] = v.x; xs[i0 + 1][b] = v.y;
                xs[i0 + 2][b] = v.z; xs[i0 + 3][b] = v.w;
            }
        }
        __syncthreads();
#pragma unroll 16
        for (int k = 0; k < 64; k++) {
            float4 w0 = *(const float4*)&ws[k][tc * 8];
            float4 w1 = *(const float4*)&ws[k][tc * 8 + 4];
            float4 hv = *(const float4*)&xs[k][tb * 4];
            float wr[8] = {w0.x, w0.y, w0.z, w0.w, w1.x, w1.y, w1.z, w1.w};
            float hr[4] = {hv.x, hv.y, hv.z, hv.w};
#pragma unroll
            for (int ci = 0; ci < 8; ci++)
#pragma unroll
                for (int bi = 0; bi < 4; bi++) acc[ci][bi] += wr[ci] * hr[bi];
        }
        __syncthreads();
    }
    float* outp = g_A0 + (size_t)t * (FH * Bz) + (size_t)colBase * Bz;
#pragma unroll
    for (int ci = 0; ci < 8; ci++) {
        float bias = bh0[colBase + tc * 8 + ci];
        float4 v = {acc[ci][0] + bias, acc[ci][1] + bias,
                    acc[ci][2] + bias, acc[ci][3] + bias};
        *(float4*)&outp[(tc * 8 + ci) * Bz + tb * 4] = v;
    }
}

// ---------------- persistent fused kernel ----------------
// smem: wt[2][16384] weights (persist) | hbuf[2][2048] | gs[4*1056]
#define SMEM_FLOATS (2 * 16384 + 2 * 2048 + 4 * 1056)
#define SMEM_BYTES  (SMEM_FLOATS * 4)

__global__ __launch_bounds__(128) void k_persist(
    const float* __restrict__ Wh0, const float* __restrict__ Wx1,
    const float* __restrict__ Wh1, const float* __restrict__ bh1,
    float* __restrict__ out)
{
    extern __shared__ float smem[];
    float* wt   = smem;
    float* hbuf = smem + 2 * 16384;
    float* gs   = smem + 2 * 16384 + 2 * 2048;

    const int tid  = threadIdx.x;
    const int cta  = blockIdx.x;
    const int lane = tid & 31;
    const int warp = tid >> 5;

    // ---- fixed job list: bjob = wjob*2 + half. wjob<64: L0 (j0=w*8); else L1 (j0=(w-64)*4)
    int nb, bj0;
    if (cta < 88) { nb = 3; bj0 = 3 * cta; } else { nb = 2; bj0 = 264 + 2 * (cta - 88); }
    int jhalf[3], jtype[3], jj0[3], jslot[3];
    int nslots = 0, slot_w[2];
    for (int u = 0; u < nb; u++) {
        int bj = bj0 + u, w = bj >> 1;
        jhalf[u] = bj & 1;
        jtype[u] = (w >= 64);
        jj0[u]   = jtype[u] ? (w - 64) * 4 : w * 8;
        int s = -1;
        for (int q = 0; q < nslots; q++) if (slot_w[q] == w) s = q;
        if (s < 0) { s = nslots; slot_w[nslots++] = w; }
        jslot[u] = s;
    }
    // ---- load weight tiles (once) ----
    for (int s = 0; s < nslots; s++) {
        int w = slot_w[s];
        float* wd = wt + s * 16384;
        if (w < 64) {
            int j0 = w * 8;
            for (int idx = tid; idx < 16384; idx += 128) {
                int k = idx >> 5, c = idx & 31, cg = c >> 3, jj = c & 7;
                wd[idx] = Wh0[(size_t)k * FH + cg * 512 + j0 + jj];
            }
        } else {
            int j0 = (w - 64) * 4;
            for (int idx = tid; idx < 16384; idx += 128) {
                int k = idx >> 4, c = idx & 15, cg = c >> 2, jj = c & 3;
                int col = cg * 512 + j0 + jj;
                wd[idx] = (k < 512) ? Wx1[(size_t)k * FH + col]
                                    : Wh1[(size_t)(k - 512) * FH + col];
            }
        }
    }
    __syncthreads();

    float carr[3][2];
#pragma unroll
    for (int u = 0; u < 3; u++) { carr[u][0] = 0.f; carr[u][1] = 0.f; }

    const int cL0 = (lane & 7) * 4, bL0 = (lane >> 3) * 8;
    const int cL1 = (lane & 3) * 4, bL1 = (lane >> 2) * 4;
    // chunk loader indices: 512 float4 per chunk, thread handles idx = tid + m*128
    unsigned ph = 0;

    for (int t = 0; t <= Tz; t++) {
        for (int u = 0; u < nb; u++) {
            int type = jtype[u];
            bool valid = type ? (t > 0) : (t < Tz);
            if (!valid) continue;                      // CTA-uniform
            int half = jhalf[u], j0 = jj0[u];
            const float* wd = wt + jslot[u] * 16384;
            int nch = type ? 16 : 8;
            int tau = t - type;

            // ---- prefetch gate-tail operands ----
            float a0r[8], soldr[2], biasr[4];
            if (!type) {
#pragma unroll
                for (int e2 = 0; e2 < 2; e2++) {
                    int e = tid + e2 * 128;
                    int jj = e >> 5, lb = e & 31;
                    int b = half * 32 + lb, j = j0 + jj;
#pragma unroll
                    for (int cg = 0; cg < 4; cg++)
                        a0r[e2 * 4 + cg] = __ldcs(&g_A0[(size_t)t * (FH * Bz) + (cg * 512 + j) * Bz + b]);
                    soldr[e2] = __ldcg(&g_s0[((t + 1) & 1) * HB + j * Bz + b]);
                }
            } else {
                int jj = tid >> 5, lb = tid & 31;
                int b = half * 32 + lb, j = j0 + jj;
#pragma unroll
                for (int cg = 0; cg < 4; cg++) biasr[cg] = __ldg(&bh1[cg * 512 + j]);
                soldr[0] = __ldcg(&g_s0[((t - 1) & 1) * HB + j * Bz + b]);   // s0(tau)
            }

            float acc[4][8];
#pragma unroll
            for (int a = 0; a < 4; a++)
#pragma unroll
                for (int b2 = 0; b2 < 8; b2++) acc[a][b2] = 0.f;

            // chunk source base
            auto chsrc = [&](int ch) -> const float* {
                if (!type) return g_h0 + ((t + 1) & 1) * HB + ch * 64 * Bz + half * 32;
                if (ch < 8) return g_s0 + ((t - 1) & 1) * HB + ch * 64 * Bz + half * 32;
                return g_h1 + (t & 1) * HB + (ch - 8) * 64 * Bz + half * 32;
            };

            float4 r[4];
            {   // load + store chunk 0
                const float* src = chsrc(0);
#pragma unroll
                for (int m = 0; m < 4; m++) {
                    int idx = tid + m * 128, kl = idx >> 3, s = idx & 7;
                    r[m] = __ldcg((const float4*)&src[kl * Bz + s * 4]);
                }
#pragma unroll
                for (int m = 0; m < 4; m++) {
                    int idx = tid + m * 128, kl = idx >> 3, s = idx & 7;
                    *(float4*)&hbuf[kl * 32 + s * 4] = r[m];
                }
                __syncthreads();
            }

            for (int ch = 0; ch < nch; ch++) {
                if (ch + 1 < nch) {
                    const float* src = chsrc(ch + 1);
#pragma unroll
                    for (int m = 0; m < 4; m++) {
                        int idx = tid + m * 128, kl = idx >> 3, s = idx & 7;
                        r[m] = __ldcg((const float4*)&src[kl * Bz + s * 4]);
                    }
                }
                const float* hb = hbuf + (ch & 1) * 2048;
                if (!type) {
#pragma unroll
                    for (int kk = 0; kk < 16; kk++) {
                        int kl = warp * 16 + kk;
                        int kg = ch * 64 + kl;
                        float4 wv  = *(const float4*)&wd[kg * 32 + cL0];
                        float4 hv0 = *(const float4*)&hb[kl * 32 + bL0];
                        float4 hv1 = *(const float4*)&hb[kl * 32 + bL0 + 4];
                        float wr[4] = {wv.x, wv.y, wv.z, wv.w};
                        float hr[8] = {hv0.x, hv0.y, hv0.z, hv0.w, hv1.x, hv1.y, hv1.z, hv1.w};
#pragma unroll
                        for (int ci = 0; ci < 4; ci++)
#pragma unroll
                            for (int bi = 0; bi < 8; bi++) acc[ci][bi] += wr[ci] * hr[bi];
                    }
                } else {
#pragma unroll
                    for (int kk = 0; kk < 16; kk++) {
                        int kl = warp * 16 + kk;
                        int kg = ch * 64 + kl;
                        float4 wv = *(const float4*)&wd[kg * 16 + cL1];
                        float4 hv = *(const float4*)&hb[kl * 32 + bL1];
                        float wr[4] = {wv.x, wv.y, wv.z, wv.w};
                        float hr[4] = {hv.x, hv.y, hv.z, hv.w};
#pragma unroll
                        for (int ci = 0; ci < 4; ci++)
#pragma unroll
                            for (int bi = 0; bi < 4; bi++) acc[ci][bi] += wr[ci] * hr[bi];
                    }
                }
                if (ch + 1 < nch) {
                    float* hn = hbuf + ((ch + 1) & 1) * 2048;
#pragma unroll
                    for (int m = 0; m < 4; m++) {
                        int idx = tid + m * 128, kl = idx >> 3, s = idx & 7;
                        *(float4*)&hn[kl * 32 + s * 4] = r[m];
                    }
                }
                __syncthreads();
            }

            // ---- cross-warp partial stage ----
            if (!type) {
#pragma unroll
                for (int ci = 0; ci < 4; ci++)
#pragma unroll
                    for (int bi = 0; bi < 8; bi++)
                        gs[warp * 1056 + (cL0 + ci) * 33 + bL0 + bi] = acc[ci][bi];
            } else {
#pragma unroll
                for (int ci = 0; ci < 4; ci++)
#pragma unroll
                    for (int bi = 0; bi < 4; bi++)
                        gs[warp * 1056 + (cL1 + ci) * 33 + bL1 + bi] = acc[ci][bi];
            }
            __syncthreads();

            // ---- fused gate tail ----
            if (!type) {
#pragma unroll
                for (int e2 = 0; e2 < 2; e2++) {
                    int e = tid + e2 * 128;
                    int jj = e >> 5, lb = e & 31;
                    int j = j0 + jj, b = half * 32 + lb;
                    float gv[4];
#pragma unroll
                    for (int cg = 0; cg < 4; cg++) {
                        float v = a0r[e2 * 4 + cg];
#pragma unroll
                        for (int w2 = 0; w2 < 4; w2++)
                            v += gs[w2 * 1056 + (cg * 8 + jj) * 33 + lb];
                        gv[cg] = v;
                    }
                    float cn  = sigf(gv[1]) * carr[u][e2] + sigf(gv[0]) * tanhf(gv[2]);
                    float hn  = sigf(gv[3]) * tanhf(cn);
                    float so  = soldr[e2];
                    float mem = so * 0.2f * (1.0f - so) + hn;
                    float sn  = (mem > 0.5f) ? 1.0f : 0.0f;
                    carr[u][e2] = cn;
                    __stcg(&g_h0[(t & 1) * HB + j * Bz + b], mem);
                    __stcg(&g_s0[(t & 1) * HB + j * Bz + b], sn);
                    if (t == Tz - 1) {
                        int bj = b * Hz + j;
                        out[OUTBASE + bj]           = sn;
                        out[OUTBASE + 32768 + bj]   = 0.0f;
                        out[OUTBASE + 65536 + bj]   = mem;
                        out[OUTBASE + 131072 + bj]  = cn;
                    }
                }
            } else {
                int jj = tid >> 5, lb = tid & 31;
                int j = j0 + jj, b = half * 32 + lb;
                float gv[4];
#pragma unroll
                for (int cg = 0; cg < 4; cg++) {
                    float v = biasr[cg];
#pragma unroll
                    for (int w2 = 0; w2 < 4; w2++)
                        v += gs[w2 * 1056 + (cg * 4 + jj) * 33 + lb];
                    gv[cg] = v;
                }
                float cn   = sigf(gv[1]) * carr[u][0] + sigf(gv[0]) * tanhf(gv[2]);
                float hraw = sigf(gv[3]) * tanhf(cn);
                float h1   = hraw * 0.2f + soldr[0];
                carr[u][0] = cn;
                __stcg(&g_h1[(tau & 1) * HB + j * Bz + b], h1);
                out[(size_t)b * (Tz * Hz) + tau * Hz + j] = h1;
                if (tau == Tz - 1) {
                    int bj = b * Hz + j;
                    out[OUTBASE + 98304 + bj]  = h1;
                    out[OUTBASE + 163840 + bj] = cn;
                }
            }
            __syncthreads();
        }
        grid_bar(++ph * NCTA);
    }
}

// ---------------- launch: 2 graph nodes ----------------
extern "C" void kernel_launch(void* const* d_in, const int* in_sizes, int n_in,
                              void* d_out, int out_size) {
    const float* x   = (const float*)d_in[0];
    const float* Wx0 = (const float*)d_in[1];
    const float* Wh0 = (const float*)d_in[2];
    const float* bh0 = (const float*)d_in[3];
    const float* Wx1 = (const float*)d_in[4];
    const float* Wh1 = (const float*)d_in[5];
    const float* bh1 = (const float*)d_in[6];
    float* out = (float*)d_out;

    static int smem_set = 0;
    if (!smem_set) {
        cudaFuncSetAttribute(k_persist,
                             cudaFuncAttributeMaxDynamicSharedMemorySize,
                             SMEM_BYTES);
        smem_set = 1;
    }

    k_phaseA<<<dim3(32, Tz), 128>>>(x, Wx0, bh0);
    k_persist<<<NCTA, 128, SMEM_BYTES>>>(Wh0, Wx1, Wh1, bh1, out);
}

// round 12
// speedup vs baseline: 1.4963x; 1.1034x over previous
#include <cuda_runtime.h>
#include <math.h>

// Problem constants
#define Bz  64
#define Tz  512
#define Iz  256
#define Hz  512
#define FH  2048   // 4*H
#define NCTA 148
#define HB  (Hz * Bz)
#define OUTBASE (Bz * Tz * Hz)   // 16777216

// ---------------- device scratch (no allocations allowed) ----------------
__device__ float g_A0[(size_t)Tz * FH * Bz];   // x@Wx0+bh0, [t][col][b]
__device__ float g_h0[2 * HB];                 // parity-buffered states, [H][B]
__device__ float g_h1[2 * HB];
__device__ float g_s0[2 * HB];
__device__ unsigned g_bar;

__device__ __forceinline__ float sigf(float x) { return 1.0f / (1.0f + __expf(-x)); }

__device__ __forceinline__ void grid_bar(unsigned target) {
    __syncthreads();
    if (threadIdx.x == 0) {
        asm volatile("red.release.gpu.global.add.u32 [%0], 1;" :: "l"(&g_bar) : "memory");
        unsigned v;
        do {
            asm volatile("ld.acquire.gpu.global.u32 %0, [%1];" : "=r"(v) : "l"(&g_bar) : "memory");
        } while (v < target);
    }
    __syncthreads();
}

// ---------------- phase A (+ state init in y==0 blocks) ----------------
__global__ __launch_bounds__(128) void k_phaseA(const float* __restrict__ x,
                                                const float* __restrict__ Wx0,
                                                const float* __restrict__ bh0) {
    __shared__ float ws[64][64];
    __shared__ float xs[64][68];
    int colTile = blockIdx.x;
    int t       = blockIdx.y;
    int tid = threadIdx.x;

    if (t == 0) {   // init states + barrier (32 blocks x 128 thr)
        int g = colTile * 128 + tid;             // 0..4095
        if (g == 0) g_bar = 0;
        for (int i = g; i < 2 * HB; i += 4096) { g_h0[i] = 0.f; g_h1[i] = 0.f; g_s0[i] = 0.f; }
    }

    int tc = tid & 7;
    int tb = tid >> 3;
    int colBase = colTile * 64;
    float acc[8][4];
#pragma unroll
    for (int a = 0; a < 8; a++)
#pragma unroll
        for (int b = 0; b < 4; b++) acc[a][b] = 0.f;

    for (int kt = 0; kt < 4; kt++) {
        int kb = kt * 64;
        for (int i = tid; i < 64 * 16; i += 128) {
            int row = i >> 4, c4 = (i & 15) << 2;
            *(float4*)&ws[row][c4] =
                *(const float4*)&Wx0[(size_t)(kb + row) * FH + colBase + c4];
        }
        {
            int b = tid >> 1, half = tid & 1;
            const float* xrow = x + ((size_t)b * Tz + t) * Iz + kb + half * 32;
#pragma unroll
            for (int q = 0; q < 8; q++) {
                float4 v = *(const float4*)(xrow + q * 4);
                int i0 = half * 32 + q * 4;
                xs[i0 + 0][b] = v.x; xs[i0 + 1][b] = v.y;
                xs[i0 + 2][b] = v.z; xs[i0 + 3][b] = v.w;
            }
        }
        __syncthreads();
#pragma unroll 16
        for (int k = 0; k < 64; k++) {
            float4 w0 = *(const float4*)&ws[k][tc * 8];
            float4 w1 = *(const float4*)&ws[k][tc * 8 + 4];
            float4 hv = *(const float4*)&xs[k][tb * 4];
            float wr[8] = {w0.x, w0.y, w0.z, w0.w, w1.x, w1.y, w1.z, w1.w};
            float hr[4] = {hv.x, hv.y, hv.z, hv.w};
#pragma unroll
            for (int ci = 0; ci < 8; ci++)
#pragma unroll
                for (int bi = 0; bi < 4; bi++) acc[ci][bi] += wr[ci] * hr[bi];
        }
        __syncthreads();
    }
    float* outp = g_A0 + (size_t)t * (FH * Bz) + (size_t)colBase * Bz;
#pragma unroll
    for (int ci = 0; ci < 8; ci++) {
        float bias = bh0[colBase + tc * 8 + ci];
        float4 v = {acc[ci][0] + bias, acc[ci][1] + bias,
                    acc[ci][2] + bias, acc[ci][3] + bias};
        *(float4*)&outp[(tc * 8 + ci) * Bz + tb * 4] = v;
    }
}

// ---------------- persistent fused kernel: 148 CTAs x 256 threads ----------------
// smem: wt[2][16384] weights (persist) | hbuf[2][2048] | gs[8*1056]
#define SMEM_FLOATS (2 * 16384 + 2 * 2048 + 8 * 1056)
#define SMEM_BYTES  (SMEM_FLOATS * 4)

__global__ __launch_bounds__(256) void k_persist(
    const float* __restrict__ Wh0, const float* __restrict__ Wx1,
    const float* __restrict__ Wh1, const float* __restrict__ bh1,
    float* __restrict__ out)
{
    extern __shared__ float smem[];
    float* wt   = smem;
    float* hbuf = smem + 2 * 16384;
    float* gs   = smem + 2 * 16384 + 2 * 2048;

    const int tid  = threadIdx.x;
    const int cta  = blockIdx.x;
    const int lane = tid & 31;
    const int warp = tid >> 5;            // 0..7

    // ---- fixed job list: bjob = wjob*2 + half. wjob<64: L0 (j0=w*8); else L1 (j0=(w-64)*4)
    int nb, bj0;
    if (cta < 88) { nb = 3; bj0 = 3 * cta; } else { nb = 2; bj0 = 264 + 2 * (cta - 88); }
    int jhalf[3], jtype[3], jj0[3], jslot[3];
    int nslots = 0, slot_w[2];
    for (int u = 0; u < nb; u++) {
        int bj = bj0 + u, w = bj >> 1;
        jhalf[u] = bj & 1;
        jtype[u] = (w >= 64);
        jj0[u]   = jtype[u] ? (w - 64) * 4 : w * 8;
        int s = -1;
        for (int q = 0; q < nslots; q++) if (slot_w[q] == w) s = q;
        if (s < 0) { s = nslots; slot_w[nslots++] = w; }
        jslot[u] = s;
    }
    // ---- load weight tiles (once) ----
    for (int s = 0; s < nslots; s++) {
        int w = slot_w[s];
        float* wd = wt + s * 16384;
        if (w < 64) {
            int j0 = w * 8;
            for (int idx = tid; idx < 16384; idx += 256) {
                int k = idx >> 5, c = idx & 31, cg = c >> 3, jj = c & 7;
                wd[idx] = Wh0[(size_t)k * FH + cg * 512 + j0 + jj];
            }
        } else {
            int j0 = (w - 64) * 4;
            for (int idx = tid; idx < 16384; idx += 256) {
                int k = idx >> 4, c = idx & 15, cg = c >> 2, jj = c & 3;
                int col = cg * 512 + j0 + jj;
                wd[idx] = (k < 512) ? Wx1[(size_t)k * FH + col]
                                    : Wh1[(size_t)(k - 512) * FH + col];
            }
        }
    }
    __syncthreads();

    float carr[3];
#pragma unroll
    for (int u = 0; u < 3; u++) carr[u] = 0.f;

    const int cL0 = (lane & 7) * 4, bL0 = (lane >> 3) * 8;
    const int cL1 = (lane & 3) * 4, bL1 = (lane >> 2) * 4;
    unsigned ph = 0;

    for (int t = 0; t <= Tz; t++) {
        for (int u = 0; u < nb; u++) {
            int type = jtype[u];
            bool valid = type ? (t > 0) : (t < Tz);
            if (!valid) continue;                      // CTA-uniform
            int half = jhalf[u], j0 = jj0[u];
            const float* wd = wt + jslot[u] * 16384;
            int nch = type ? 16 : 8;
            int tau = t - type;

            // ---- prefetch gate-tail operands (one eval per thread) ----
            float a0r[4], sold = 0.f, biasr[4];
            if (!type) {
                int jj = tid >> 5, lb = tid & 31;        // 8 x 32 = 256 evals
                int b = half * 32 + lb, j = j0 + jj;
#pragma unroll
                for (int cg = 0; cg < 4; cg++)
                    a0r[cg] = __ldcs(&g_A0[(size_t)t * (FH * Bz) + (cg * 512 + j) * Bz + b]);
                sold = __ldcg(&g_s0[((t + 1) & 1) * HB + j * Bz + b]);
            } else if (tid < 128) {
                int jj = tid >> 5, lb = tid & 31;        // 4 x 32 = 128 evals
                int b = half * 32 + lb, j = j0 + jj;
#pragma unroll
                for (int cg = 0; cg < 4; cg++) biasr[cg] = __ldg(&bh1[cg * 512 + j]);
                sold = __ldcg(&g_s0[((t - 1) & 1) * HB + j * Bz + b]);   // s0(tau)
            }

            float acc[4][8];
#pragma unroll
            for (int a = 0; a < 4; a++)
#pragma unroll
                for (int b2 = 0; b2 < 8; b2++) acc[a][b2] = 0.f;

            auto chsrc = [&](int ch) -> const float* {
                if (!type) return g_h0 + ((t + 1) & 1) * HB + ch * 64 * Bz + half * 32;
                if (ch < 8) return g_s0 + ((t - 1) & 1) * HB + ch * 64 * Bz + half * 32;
                return g_h1 + (t & 1) * HB + (ch - 8) * 64 * Bz + half * 32;
            };

            float4 r[2];
            {   // load + store chunk 0 (512 float4 over 256 threads)
                const float* src = chsrc(0);
#pragma unroll
                for (int m = 0; m < 2; m++) {
                    int idx = tid + m * 256, kl = idx >> 3, s = idx & 7;
                    r[m] = __ldcg((const float4*)&src[kl * Bz + s * 4]);
                }
#pragma unroll
                for (int m = 0; m < 2; m++) {
                    int idx = tid + m * 256, kl = idx >> 3, s = idx & 7;
                    *(float4*)&hbuf[kl * 32 + s * 4] = r[m];
                }
                __syncthreads();
            }

            for (int ch = 0; ch < nch; ch++) {
                if (ch + 1 < nch) {
                    const float* src = chsrc(ch + 1);
#pragma unroll
                    for (int m = 0; m < 2; m++) {
                        int idx = tid + m * 256, kl = idx >> 3, s = idx & 7;
                        r[m] = __ldcg((const float4*)&src[kl * Bz + s * 4]);
                    }
                }
                const float* hb = hbuf + (ch & 1) * 2048;
                if (!type) {
#pragma unroll
                    for (int kk = 0; kk < 8; kk++) {
                        int kl = warp * 8 + kk;
                        int kg = ch * 64 + kl;
                        float4 wv  = *(const float4*)&wd[kg * 32 + cL0];
                        float4 hv0 = *(const float4*)&hb[kl * 32 + bL0];
                        float4 hv1 = *(const float4*)&hb[kl * 32 + bL0 + 4];
                        float wr[4] = {wv.x, wv.y, wv.z, wv.w};
                        float hr[8] = {hv0.x, hv0.y, hv0.z, hv0.w, hv1.x, hv1.y, hv1.z, hv1.w};
#pragma unroll
                        for (int ci = 0; ci < 4; ci++)
#pragma unroll
                            for (int bi = 0; bi < 8; bi++) acc[ci][bi] += wr[ci] * hr[bi];
                    }
                } else {
#pragma unroll
                    for (int kk = 0; kk < 8; kk++) {
                        int kl = warp * 8 + kk;
                        int kg = ch * 64 + kl;
                        float4 wv = *(const float4*)&wd[kg * 16 + cL1];
                        float4 hv = *(const float4*)&hb[kl * 32 + bL1];
                        float wr[4] = {wv.x, wv.y, wv.z, wv.w};
                        float hr[4] = {hv.x, hv.y, hv.z, hv.w};
#pragma unroll
                        for (int ci = 0; ci < 4; ci++)
#pragma unroll
                            for (int bi = 0; bi < 4; bi++) acc[ci][bi] += wr[ci] * hr[bi];
                    }
                }
                if (ch + 1 < nch) {
                    float* hn = hbuf + ((ch + 1) & 1) * 2048;
#pragma unroll
                    for (int m = 0; m < 2; m++) {
                        int idx = tid + m * 256, kl = idx >> 3, s = idx & 7;
                        *(float4*)&hn[kl * 32 + s * 4] = r[m];
                    }
                }
                __syncthreads();
            }

            // ---- cross-warp partial stage (8 slices) ----
            if (!type) {
#pragma unroll
                for (int ci = 0; ci < 4; ci++)
#pragma unroll
                    for (int bi = 0; bi < 8; bi++)
                        gs[warp * 1056 + (cL0 + ci) * 33 + bL0 + bi] = acc[ci][bi];
            } else {
#pragma unroll
                for (int ci = 0; ci < 4; ci++)
#pragma unroll
                    for (int bi = 0; bi < 4; bi++)
                        gs[warp * 1056 + (cL1 + ci) * 33 + bL1 + bi] = acc[ci][bi];
            }
            __syncthreads();

            // ---- fused gate tail ----
            if (!type) {
                int jj = tid >> 5, lb = tid & 31;
                int j = j0 + jj, b = half * 32 + lb;
                float gv[4];
#pragma unroll
                for (int cg = 0; cg < 4; cg++) {
                    float v = a0r[cg];
#pragma unroll
                    for (int w2 = 0; w2 < 8; w2++)
                        v += gs[w2 * 1056 + (cg * 8 + jj) * 33 + lb];
                    gv[cg] = v;
                }
                float cn  = sigf(gv[1]) * carr[u] + sigf(gv[0]) * tanhf(gv[2]);
                float hn  = sigf(gv[3]) * tanhf(cn);
                float mem = sold * 0.2f * (1.0f - sold) + hn;
                float sn  = (mem > 0.5f) ? 1.0f : 0.0f;
                carr[u] = cn;
                __stcg(&g_h0[(t & 1) * HB + j * Bz + b], mem);
                __stcg(&g_s0[(t & 1) * HB + j * Bz + b], sn);
                if (t == Tz - 1) {
                    int bj = b * Hz + j;
                    out[OUTBASE + bj]           = sn;
                    out[OUTBASE + 32768 + bj]   = 0.0f;
                    out[OUTBASE + 65536 + bj]   = mem;
                    out[OUTBASE + 131072 + bj]  = cn;
                }
            } else if (tid < 128) {
                int jj = tid >> 5, lb = tid & 31;
                int j = j0 + jj, b = half * 32 + lb;
                float gv[4];
#pragma unroll
                for (int cg = 0; cg < 4; cg++) {
                    float v = biasr[cg];
#pragma unroll
                    for (int w2 = 0; w2 < 8; w2++)
                        v += gs[w2 * 1056 + (cg * 4 + jj) * 33 + lb];
                    gv[cg] = v;
                }
                float cn   = sigf(gv[1]) * carr[u] + sigf(gv[0]) * tanhf(gv[2]);
                float hraw = sigf(gv[3]) * tanhf(cn);
                float h1   = hraw * 0.2f + sold;
                carr[u] = cn;
                __stcg(&g_h1[(tau & 1) * HB + j * Bz + b], h1);
                out[(size_t)b * (Tz * Hz) + tau * Hz + j] = h1;
                if (tau == Tz - 1) {
                    int bj = b * Hz + j;
                    out[OUTBASE + 98304 + bj]  = h1;
                    out[OUTBASE + 163840 + bj] = cn;
                }
            }
            __syncthreads();
        }
        grid_bar(++ph * NCTA);
    }
}

// ---------------- launch: 2 graph nodes ----------------
extern "C" void kernel_launch(void* const* d_in, const int* in_sizes, int n_in,
                              void* d_out, int out_size) {
    const float* x   = (const float*)d_in[0];
    const float* Wx0 = (const float*)d_in[1];
    const float* Wh0 = (const float*)d_in[2];
    const float* bh0 = (const float*)d_in[3];
    const float* Wx1 = (const float*)d_in[4];
    const float* Wh1 = (const float*)d_in[5];
    const float* bh1 = (const float*)d_in[6];
    float* out = (float*)d_out;

    static int smem_set = 0;
    if (!smem_set) {
        cudaFuncSetAttribute(k_persist,
                             cudaFuncAttributeMaxDynamicSharedMemorySize,
                             SMEM_BYTES);
        smem_set = 1;
    }

    k_phaseA<<<dim3(32, Tz), 128>>>(x, Wx0, bh0);
    k_persist<<<NCTA, 256, SMEM_BYTES>>>(Wh0, Wx1, Wh1, bh1, out);
}